// round 1
// baseline (speedup 1.0000x reference)
#include <cuda_runtime.h>
#include <cuda_bf16.h>
#include <math.h>

// Problem constants
#define B_    2
#define S_    2048
#define D_    2048
#define H_    16
#define HD_   128
#define M_TOK (B_ * S_)          // 4096 tokens
#define QKV_N (3 * H_ * HD_)     // 6144
#define DM_   (H_ * HD_)         // 2048 (model dim of attn out)

// ---------------------------------------------------------------------------
// Scratch (no allocation allowed -> __device__ globals)
// ---------------------------------------------------------------------------
__device__ float g_qkv[(size_t)M_TOK * QKV_N];   // 100.7 MB
__device__ float g_attn[(size_t)M_TOK * DM_];    // 33.6 MB
__device__ float g_cos[S_ * (HD_ / 2)];
__device__ float g_sin[S_ * (HD_ / 2)];

// ---------------------------------------------------------------------------
// SGEMM: C[M,N] = A[M,K] @ B[K,N], all row-major fp32.
// 128x128 block tile, BK=16, 8x8 per thread, 256 threads,
// float4 global loads, register prefetch to overlap LDG with compute.
// ---------------------------------------------------------------------------
#define BM 128
#define BN 128
#define BK 16
#define TM 8
#define TN 8

__global__ __launch_bounds__(256) void sgemm_kernel(
    const float* __restrict__ A, const float* __restrict__ B,
    float* __restrict__ C, int M, int N, int K)
{
    __shared__ float As[BK][BM + 4];   // transposed, padded vs bank conflicts
    __shared__ float Bs[BK][BN];

    const int tid = threadIdx.x;
    const int bm = blockIdx.y * BM;
    const int bn = blockIdx.x * BN;

    const int a_row = tid >> 2;           // 0..63 (+64 for second slot)
    const int a_col = (tid & 3) << 2;     // 0,4,8,12 within BK
    const int b_row = tid >> 5;           // 0..7 (+8 for second slot)
    const int b_col = (tid & 31) << 2;    // 0..124

    const int t_row = (tid >> 4) << 3;    // 0..120, step 8
    const int t_col = (tid & 15) << 3;

    const float* Ap = A + (size_t)bm * K;
    const float* Bp = B + bn;

    float acc[TM][TN];
#pragma unroll
    for (int i = 0; i < TM; ++i)
#pragma unroll
        for (int j = 0; j < TN; ++j) acc[i][j] = 0.f;

    float4 apf[2], bpf[2];
#pragma unroll
    for (int p = 0; p < 2; ++p) {
        apf[p] = *(const float4*)(Ap + (size_t)(a_row + 64 * p) * K + a_col);
        bpf[p] = *(const float4*)(Bp + (size_t)(b_row + 8 * p) * N + b_col);
    }

    for (int kt = 0; kt < K; kt += BK) {
#pragma unroll
        for (int p = 0; p < 2; ++p) {
            As[a_col + 0][a_row + 64 * p] = apf[p].x;
            As[a_col + 1][a_row + 64 * p] = apf[p].y;
            As[a_col + 2][a_row + 64 * p] = apf[p].z;
            As[a_col + 3][a_row + 64 * p] = apf[p].w;
            *(float4*)(&Bs[b_row + 8 * p][b_col]) = bpf[p];
        }
        __syncthreads();

        const int kn = kt + BK;
        if (kn < K) {
#pragma unroll
            for (int p = 0; p < 2; ++p) {
                apf[p] = *(const float4*)(Ap + (size_t)(a_row + 64 * p) * K + kn + a_col);
                bpf[p] = *(const float4*)(Bp + (size_t)(kn + b_row + 8 * p) * N + b_col);
            }
        }

#pragma unroll
        for (int k = 0; k < BK; ++k) {
            float ra[TM], rb[TN];
            *(float4*)(ra)     = *(const float4*)(&As[k][t_row]);
            *(float4*)(ra + 4) = *(const float4*)(&As[k][t_row + 4]);
            *(float4*)(rb)     = *(const float4*)(&Bs[k][t_col]);
            *(float4*)(rb + 4) = *(const float4*)(&Bs[k][t_col + 4]);
#pragma unroll
            for (int i = 0; i < TM; ++i)
#pragma unroll
                for (int j = 0; j < TN; ++j)
                    acc[i][j] = fmaf(ra[i], rb[j], acc[i][j]);
        }
        __syncthreads();
    }

#pragma unroll
    for (int i = 0; i < TM; ++i) {
        float* crow = C + (size_t)(bm + t_row + i) * N + bn + t_col;
        float4 o0 = make_float4(acc[i][0], acc[i][1], acc[i][2], acc[i][3]);
        float4 o1 = make_float4(acc[i][4], acc[i][5], acc[i][6], acc[i][7]);
        *(float4*)(crow)     = o0;
        *(float4*)(crow + 4) = o1;
    }
}

// ---------------------------------------------------------------------------
// RoPE cos/sin table (fp32 angle like the reference; accurate trig via double)
// ---------------------------------------------------------------------------
__global__ void rope_table_kernel(float* __restrict__ ct, float* __restrict__ st)
{
    int idx = blockIdx.x * blockDim.x + threadIdx.x;
    if (idx >= S_ * 64) return;
    int d = idx & 63;
    int s = idx >> 6;
    float inv_freq = 1.0f / powf(10000.0f, (float)d * (1.0f / 64.0f));
    float ang = (float)s * inv_freq;          // fp32, matching the reference
    ct[idx] = (float)cos((double)ang);
    st[idx] = (float)sin((double)ang);
}

// ---------------------------------------------------------------------------
// Apply rotate-half RoPE in-place to q and k regions of qkv.
// One thread per (token, which∈{q,k}, head, pair d<64).
// ---------------------------------------------------------------------------
__global__ void rope_kernel(float* __restrict__ qkv,
                            const float* __restrict__ ct,
                            const float* __restrict__ st)
{
    int idx = blockIdx.x * blockDim.x + threadIdx.x;
    if (idx >= M_TOK * 2 * H_ * 64) return;
    int d     = idx & 63;
    int h     = (idx >> 6) & 15;
    int which = (idx >> 10) & 1;
    int bs    = idx >> 11;
    int s     = bs & (S_ - 1);

    size_t base = (size_t)bs * QKV_N + (size_t)which * DM_ + h * HD_ + d;
    float lo = qkv[base];
    float hi = qkv[base + 64];
    float c  = ct[(s << 6) + d];
    float sn = st[(s << 6) + d];
    qkv[base]      = lo * c - hi * sn;
    qkv[base + 64] = hi * c + lo * sn;
}

// ---------------------------------------------------------------------------
// Causal flash attention, fp32.
// Grid: (S/64, H, B). 256 threads. 64x64 tiles, HD=128.
// Thread layout: tx = tid%16 (cols), ty = tid/16 (rows).
//   Scores: thread owns rows {ty+16i}, cols {tx+16j}  (4x4)
//   PV:     thread owns rows {ty+16i}, cols {tx*8..tx*8+7} (4x8 of HD)
// Heavy-diagonal blocks launched first (qb reversed) for causal balance.
// ---------------------------------------------------------------------------
#define AQ    64
#define AKV   64
#define QKSTR 132
#define PSTR  65
#define ATT_SMEM ((3 * AQ * QKSTR + AQ * PSTR) * 4)   // 118016 B

__global__ __launch_bounds__(256) void attn_kernel(
    const float* __restrict__ qkv, float* __restrict__ out)
{
    extern __shared__ float sm[];
    float* Qs = sm;
    float* Ks = Qs + AQ * QKSTR;
    float* Vs = Ks + AKV * QKSTR;
    float* Ps = Vs + AKV * QKSTR;

    const int qb  = (gridDim.x - 1) - blockIdx.x;   // heavy tiles first
    const int h   = blockIdx.y;
    const int b   = blockIdx.z;
    const int tid = threadIdx.x;
    const int tx  = tid & 15;
    const int ty  = tid >> 4;

    const int q0 = qb * AQ;
    const size_t tok0 = (size_t)b * S_;

    // Load Q tile [64][128] (coalesced float4, one warp per row)
    {
        const float* qbase = qkv + (tok0 + q0) * QKV_N + h * HD_;
#pragma unroll
        for (int it = 0; it < 8; ++it) {
            int slot = tid + it * 256;
            int r  = slot >> 5;
            int d4 = (slot & 31) << 2;
            *(float4*)(Qs + r * QKSTR + d4) =
                *(const float4*)(qbase + (size_t)r * QKV_N + d4);
        }
    }

    float m_i[4], l_i[4], o_acc[4][8];
#pragma unroll
    for (int i = 0; i < 4; ++i) {
        m_i[i] = -INFINITY;
        l_i[i] = 0.f;
#pragma unroll
        for (int k = 0; k < 8; ++k) o_acc[i][k] = 0.f;
    }

    const float scale = 0.08838834764831845f;   // 128^-0.5

    for (int kb = 0; kb <= qb; ++kb) {
        __syncthreads();   // previous iteration done reading K/V/P
        {
            const float* kbase = qkv + (tok0 + kb * AKV) * QKV_N + DM_ + h * HD_;
            const float* vbase = kbase + DM_;
#pragma unroll
            for (int it = 0; it < 8; ++it) {
                int slot = tid + it * 256;
                int r  = slot >> 5;
                int d4 = (slot & 31) << 2;
                *(float4*)(Ks + r * QKSTR + d4) =
                    *(const float4*)(kbase + (size_t)r * QKV_N + d4);
                *(float4*)(Vs + r * QKSTR + d4) =
                    *(const float4*)(vbase + (size_t)r * QKV_N + d4);
            }
        }
        __syncthreads();   // tiles ready (covers Q on first iteration)

        // ---- scores S = Q K^T ----
        float s[4][4];
#pragma unroll
        for (int i = 0; i < 4; ++i)
#pragma unroll
            for (int j = 0; j < 4; ++j) s[i][j] = 0.f;

#pragma unroll 4
        for (int d4 = 0; d4 < HD_; d4 += 4) {
            float4 qv[4], kv[4];
#pragma unroll
            for (int i = 0; i < 4; ++i)
                qv[i] = *(const float4*)(Qs + (ty + 16 * i) * QKSTR + d4);
#pragma unroll
            for (int j = 0; j < 4; ++j)
                kv[j] = *(const float4*)(Ks + (tx + 16 * j) * QKSTR + d4);
#pragma unroll
            for (int i = 0; i < 4; ++i)
#pragma unroll
                for (int j = 0; j < 4; ++j) {
                    s[i][j] = fmaf(qv[i].x, kv[j].x, s[i][j]);
                    s[i][j] = fmaf(qv[i].y, kv[j].y, s[i][j]);
                    s[i][j] = fmaf(qv[i].z, kv[j].z, s[i][j]);
                    s[i][j] = fmaf(qv[i].w, kv[j].w, s[i][j]);
                }
        }

        // ---- scale + causal mask (only the diagonal block needs masking) ----
        const bool diag = (kb == qb);
#pragma unroll
        for (int i = 0; i < 4; ++i) {
            int rg = q0 + ty + 16 * i;
#pragma unroll
            for (int j = 0; j < 4; ++j) {
                int cg = kb * AKV + tx + 16 * j;
                s[i][j] = (diag && (cg > rg)) ? -INFINITY : s[i][j] * scale;
            }
        }

        // ---- online softmax update ----
#pragma unroll
        for (int i = 0; i < 4; ++i) {
            float mx = fmaxf(fmaxf(s[i][0], s[i][1]), fmaxf(s[i][2], s[i][3]));
#pragma unroll
            for (int off = 8; off > 0; off >>= 1)
                mx = fmaxf(mx, __shfl_xor_sync(0xffffffffu, mx, off, 16));
            float m_new = fmaxf(m_i[i], mx);
            float alpha = __expf(m_i[i] - m_new);   // 0 on first tile
            float psum  = 0.f;
            int   r     = ty + 16 * i;
#pragma unroll
            for (int j = 0; j < 4; ++j) {
                float p = __expf(s[i][j] - m_new);  // 0 for masked entries
                psum += p;
                Ps[r * PSTR + tx + 16 * j] = p;
            }
#pragma unroll
            for (int off = 8; off > 0; off >>= 1)
                psum += __shfl_xor_sync(0xffffffffu, psum, off, 16);
            l_i[i] = l_i[i] * alpha + psum;
            m_i[i] = m_new;
#pragma unroll
            for (int k = 0; k < 8; ++k) o_acc[i][k] *= alpha;
        }
        __syncthreads();   // P tile visible to everyone

        // ---- O += P @ V ----
#pragma unroll 4
        for (int k0 = 0; k0 < AKV; ++k0) {
            float4 v0 = *(const float4*)(Vs + k0 * QKSTR + tx * 8);
            float4 v1 = *(const float4*)(Vs + k0 * QKSTR + tx * 8 + 4);
#pragma unroll
            for (int i = 0; i < 4; ++i) {
                float p = Ps[(ty + 16 * i) * PSTR + k0];
                o_acc[i][0] = fmaf(p, v0.x, o_acc[i][0]);
                o_acc[i][1] = fmaf(p, v0.y, o_acc[i][1]);
                o_acc[i][2] = fmaf(p, v0.z, o_acc[i][2]);
                o_acc[i][3] = fmaf(p, v0.w, o_acc[i][3]);
                o_acc[i][4] = fmaf(p, v1.x, o_acc[i][4]);
                o_acc[i][5] = fmaf(p, v1.y, o_acc[i][5]);
                o_acc[i][6] = fmaf(p, v1.z, o_acc[i][6]);
                o_acc[i][7] = fmaf(p, v1.w, o_acc[i][7]);
            }
        }
    }

    // ---- finalize: divide by l, write [token, h*128 + col] ----
#pragma unroll
    for (int i = 0; i < 4; ++i) {
        float inv = 1.f / l_i[i];
        int   r   = ty + 16 * i;
        float* orow = out + (tok0 + q0 + r) * (size_t)DM_ + h * HD_ + tx * 8;
        float4 o0 = make_float4(o_acc[i][0] * inv, o_acc[i][1] * inv,
                                o_acc[i][2] * inv, o_acc[i][3] * inv);
        float4 o1 = make_float4(o_acc[i][4] * inv, o_acc[i][5] * inv,
                                o_acc[i][6] * inv, o_acc[i][7] * inv);
        *(float4*)(orow)     = o0;
        *(float4*)(orow + 4) = o1;
    }
}

// ---------------------------------------------------------------------------
// Launch
// ---------------------------------------------------------------------------
extern "C" void kernel_launch(void* const* d_in, const int* in_sizes, int n_in,
                              void* d_out, int out_size)
{
    (void)in_sizes; (void)n_in; (void)out_size;
    const float* x     = (const float*)d_in[0];
    const float* W_qkv = (const float*)d_in[1];
    const float* W_o   = (const float*)d_in[2];
    float* out = (float*)d_out;

    float *qkv, *attn, *ct, *st;
    cudaGetSymbolAddress((void**)&qkv,  g_qkv);
    cudaGetSymbolAddress((void**)&attn, g_attn);
    cudaGetSymbolAddress((void**)&ct,   g_cos);
    cudaGetSymbolAddress((void**)&st,   g_sin);

    // RoPE table (independent of GEMM1, tiny)
    rope_table_kernel<<<(S_ * 64 + 255) / 256, 256>>>(ct, st);

    // qkv = x @ W_qkv   [4096 x 6144]
    sgemm_kernel<<<dim3(QKV_N / BN, M_TOK / BM), 256>>>(
        x, W_qkv, qkv, M_TOK, QKV_N, D_);

    // RoPE on q,k in place
    rope_kernel<<<(M_TOK * 2 * H_ * 64) / 256, 256>>>(qkv, ct, st);

    // causal attention -> attn [4096 x 2048]
    cudaFuncSetAttribute(attn_kernel,
                         cudaFuncAttributeMaxDynamicSharedMemorySize, ATT_SMEM);
    attn_kernel<<<dim3(S_ / AQ, H_, B_), 256, ATT_SMEM>>>(qkv, attn);

    // out = attn @ W_o  [4096 x 2048]
    sgemm_kernel<<<dim3(D_ / BN, M_TOK / BM), 256>>>(
        attn, W_o, out, M_TOK, D_, D_);
}

// round 3
// speedup vs baseline: 1.5561x; 1.5561x over previous
#include <cuda_runtime.h>
#include <cuda_bf16.h>
#include <math.h>
#include <stdint.h>

// Problem constants
#define B_    2
#define S_    2048
#define D_    2048
#define H_    16
#define HD_   128
#define M_TOK (B_ * S_)          // 4096 tokens
#define QKV_N (3 * H_ * HD_)     // 6144
#define DM_   (H_ * HD_)         // 2048

// ---------------------------------------------------------------------------
// Scratch (__device__ globals; no allocation allowed)
// ---------------------------------------------------------------------------
__device__ float g_qkv[(size_t)M_TOK * QKV_N];            // 100.7 MB
__device__ float g_attn[(size_t)M_TOK * DM_];             // 33.6 MB
__device__ float g_cos[S_ * (HD_ / 2)];
__device__ float g_sin[S_ * (HD_ / 2)];
__device__ __nv_bfloat16 g_Ah[(size_t)M_TOK * D_];        // A (x or attn) hi
__device__ __nv_bfloat16 g_Al[(size_t)M_TOK * D_];        // A lo
__device__ __nv_bfloat16 g_Bh[(size_t)QKV_N * D_];        // W_qkv^T hi  [N][K]
__device__ __nv_bfloat16 g_Bl[(size_t)QKV_N * D_];
__device__ __nv_bfloat16 g_Woh[(size_t)DM_ * D_];         // W_o^T hi    [N][K]
__device__ __nv_bfloat16 g_Wol[(size_t)DM_ * D_];

// ---------------------------------------------------------------------------
// Arch-generic PTX helpers (NO tcgen05 — compute_103 target rejects it)
// ---------------------------------------------------------------------------
__device__ __forceinline__ uint32_t smem_u32(const void* p) {
    uint32_t a;
    asm("{ .reg .u64 t; cvta.to.shared.u64 t, %1; cvt.u32.u64 %0, t; }"
        : "=r"(a) : "l"(p));
    return a;
}
#define CP16(dst, src) \
    asm volatile("cp.async.cg.shared.global [%0], [%1], 16;" :: "r"(dst), "l"(src) : "memory")
#define CP_COMMIT() asm volatile("cp.async.commit_group;" ::: "memory")
#define CP_WAIT(n)  asm volatile("cp.async.wait_group %0;" :: "n"(n) : "memory")

__device__ __forceinline__ void ldsm4(uint32_t* r, uint32_t addr) {
    asm volatile("ldmatrix.sync.aligned.m8n8.x4.shared.b16 {%0,%1,%2,%3}, [%4];"
                 : "=r"(r[0]), "=r"(r[1]), "=r"(r[2]), "=r"(r[3]) : "r"(addr));
}
__device__ __forceinline__ void mma16816(float* c, const uint32_t* a, const uint32_t* b) {
    asm volatile(
        "mma.sync.aligned.m16n8k16.row.col.f32.bf16.bf16.f32 "
        "{%0,%1,%2,%3}, {%4,%5,%6,%7}, {%8,%9}, {%0,%1,%2,%3};"
        : "+f"(c[0]), "+f"(c[1]), "+f"(c[2]), "+f"(c[3])
        : "r"(a[0]), "r"(a[1]), "r"(a[2]), "r"(a[3]), "r"(b[0]), "r"(b[1]));
}

// ---------------------------------------------------------------------------
// bf16x3 MMA GEMM:  C[M,N] = A[M,K] @ B^T  with B stored [N][K].
// CTA 128x128, BK=32, 8 warps (warp tile 32x64), 2-stage cp.async pipeline.
// Per k-step: D += Ah*Bh + Ah*Bl + Al*Bh  (fp32 accum; residual ~2^-16)
// ---------------------------------------------------------------------------
#define GSTR  40                       // smem row stride in bf16 (80B: ldsm conflict-free)
#define TILE_E (128 * GSTR)            // 5120 elems per tile
#define STG_E  (4 * TILE_E)            // elems per stage (Ah,Al,Bh,Bl)
#define GEMM_SMEM (2 * STG_E * 2)      // 81920 bytes

__global__ __launch_bounds__(256) void gemm_mma_kernel(
    const __nv_bfloat16* __restrict__ Ah, const __nv_bfloat16* __restrict__ Al,
    const __nv_bfloat16* __restrict__ Bh, const __nv_bfloat16* __restrict__ Bl,
    float* __restrict__ C, int M, int N, int K)
{
    extern __shared__ __nv_bfloat16 sm[];
    const uint32_t sbase = smem_u32(sm);
    const int tid  = threadIdx.x;
    const int lane = tid & 31;
    const int wid  = tid >> 5;
    const int bm = blockIdx.y * 128;
    const int bn = blockIdx.x * 128;
    const int wm = (wid & 3) * 32;     // warp M offset
    const int wn = (wid >> 2) * 64;    // warp N offset

    float acc[2][8][4];
#pragma unroll
    for (int mt = 0; mt < 2; ++mt)
#pragma unroll
        for (int nt = 0; nt < 8; ++nt)
#pragma unroll
            for (int v = 0; v < 4; ++v) acc[mt][nt][v] = 0.f;

    auto load_chunk = [&](int stage, int kc) {
#pragma unroll
        for (int j = 0; j < 8; ++j) {
            int s = tid + j * 256;           // 2048 16B-chunks total
            int tile = s >> 9;               // 0:Ah 1:Al 2:Bh 3:Bl
            int r = (s >> 2) & 127;
            int c = s & 3;
            const __nv_bfloat16* p =
                (tile == 0) ? Ah : (tile == 1) ? Al : (tile == 2) ? Bh : Bl;
            int rb = (tile < 2) ? bm : bn;
            const __nv_bfloat16* src = p + (size_t)(rb + r) * K + kc + c * 8;
            uint32_t dst = sbase + (uint32_t)(stage * STG_E + tile * TILE_E +
                                              r * GSTR + c * 8) * 2u;
            CP16(dst, src);
        }
    };

    const int NC = K / 32;
    load_chunk(0, 0);
    CP_COMMIT();

    for (int i = 0; i < NC; ++i) {
        if (i + 1 < NC) {
            load_chunk((i + 1) & 1, (i + 1) * 32);
            CP_COMMIT();
            CP_WAIT(1);
        } else {
            CP_WAIT(0);
        }
        __syncthreads();

        const uint32_t sA  = sbase + (uint32_t)((i & 1) * STG_E) * 2u;
        const uint32_t dAl = TILE_E * 2u;        // byte offsets between tiles
        const uint32_t dB  = 2u * TILE_E * 2u;

#pragma unroll
        for (int ks = 0; ks < 32; ks += 16) {
            uint32_t ah[2][4], al[2][4], bh[8][2], bl[8][2];
#pragma unroll
            for (int mt = 0; mt < 2; ++mt) {
                uint32_t ra = sA + (uint32_t)((wm + mt * 16 + (lane & 15)) * GSTR +
                                              ks + (lane >> 4) * 8) * 2u;
                ldsm4(ah[mt], ra);
                ldsm4(al[mt], ra + dAl);
            }
#pragma unroll
            for (int p = 0; p < 4; ++p) {
                uint32_t rb = sA + dB + (uint32_t)((wn + p * 16 + (lane & 15)) * GSTR +
                                                   ks + (lane >> 4) * 8) * 2u;
                uint32_t t[4];
                ldsm4(t, rb);
                bh[2 * p][0] = t[0]; bh[2 * p + 1][0] = t[1];
                bh[2 * p][1] = t[2]; bh[2 * p + 1][1] = t[3];
                ldsm4(t, rb + dAl);
                bl[2 * p][0] = t[0]; bl[2 * p + 1][0] = t[1];
                bl[2 * p][1] = t[2]; bl[2 * p + 1][1] = t[3];
            }
            // split-ordered issue: RAW distance on each acc = 16 MMAs
#pragma unroll
            for (int mt = 0; mt < 2; ++mt)
#pragma unroll
                for (int nt = 0; nt < 8; ++nt) mma16816(acc[mt][nt], ah[mt], bh[nt]);
#pragma unroll
            for (int mt = 0; mt < 2; ++mt)
#pragma unroll
                for (int nt = 0; nt < 8; ++nt) mma16816(acc[mt][nt], ah[mt], bl[nt]);
#pragma unroll
            for (int mt = 0; mt < 2; ++mt)
#pragma unroll
                for (int nt = 0; nt < 8; ++nt) mma16816(acc[mt][nt], al[mt], bh[nt]);
        }
        __syncthreads();
    }

    // epilogue: fragment layout -> global fp32
#pragma unroll
    for (int mt = 0; mt < 2; ++mt) {
        int row = bm + wm + mt * 16 + (lane >> 2);
#pragma unroll
        for (int nt = 0; nt < 8; ++nt) {
            int col = bn + wn + nt * 8 + (lane & 3) * 2;
            *(float2*)&C[(size_t)row * N + col] =
                make_float2(acc[mt][nt][0], acc[mt][nt][1]);
            *(float2*)&C[(size_t)(row + 8) * N + col] =
                make_float2(acc[mt][nt][2], acc[mt][nt][3]);
        }
    }
}

// ---------------------------------------------------------------------------
// fp32 -> bf16 hi/lo split (elementwise)
// ---------------------------------------------------------------------------
__global__ void conv_split_kernel(const float* __restrict__ X,
                                  __nv_bfloat16* __restrict__ Xh,
                                  __nv_bfloat16* __restrict__ Xl, int n4)
{
    int i = blockIdx.x * blockDim.x + threadIdx.x;
    if (i >= n4) return;
    float4 v = *(const float4*)(X + (size_t)i * 4);
    __nv_bfloat162 h01 = __floats2bfloat162_rn(v.x, v.y);
    __nv_bfloat162 h23 = __floats2bfloat162_rn(v.z, v.w);
    float2 f01 = __bfloat1622float2(h01);
    float2 f23 = __bfloat1622float2(h23);
    __nv_bfloat162 l01 = __floats2bfloat162_rn(v.x - f01.x, v.y - f01.y);
    __nv_bfloat162 l23 = __floats2bfloat162_rn(v.z - f23.x, v.w - f23.y);
    *(__nv_bfloat162*)(Xh + (size_t)i * 4)     = h01;
    *(__nv_bfloat162*)(Xh + (size_t)i * 4 + 2) = h23;
    *(__nv_bfloat162*)(Xl + (size_t)i * 4)     = l01;
    *(__nv_bfloat162*)(Xl + (size_t)i * 4 + 2) = l23;
}

// ---------------------------------------------------------------------------
// fp32 W[R,C] -> transposed bf16 hi/lo T[C,R]
// ---------------------------------------------------------------------------
__global__ __launch_bounds__(256) void conv_tsplit_kernel(
    const float* __restrict__ W, int R, int C,
    __nv_bfloat16* __restrict__ Th, __nv_bfloat16* __restrict__ Tl)
{
    __shared__ float t[32][33];
    const int c0 = blockIdx.x * 32, r0 = blockIdx.y * 32;
    const int tx = threadIdx.x & 31, ty = threadIdx.x >> 5;
#pragma unroll
    for (int i = 0; i < 32; i += 8)
        t[ty + i][tx] = W[(size_t)(r0 + ty + i) * C + c0 + tx];
    __syncthreads();
#pragma unroll
    for (int i = 0; i < 32; i += 8) {
        float v = t[tx][ty + i];
        __nv_bfloat16 h = __float2bfloat16(v);
        __nv_bfloat16 l = __float2bfloat16(v - __bfloat162float(h));
        size_t o = (size_t)(c0 + ty + i) * R + r0 + tx;
        Th[o] = h;
        Tl[o] = l;
    }
}

// ---------------------------------------------------------------------------
// RoPE table + apply
// ---------------------------------------------------------------------------
__global__ void rope_table_kernel(float* __restrict__ ct, float* __restrict__ st)
{
    int idx = blockIdx.x * blockDim.x + threadIdx.x;
    if (idx >= S_ * 64) return;
    int d = idx & 63;
    int s = idx >> 6;
    float inv_freq = 1.0f / powf(10000.0f, (float)d * (1.0f / 64.0f));
    float ang = (float)s * inv_freq;
    ct[idx] = (float)cos((double)ang);
    st[idx] = (float)sin((double)ang);
}

__global__ void rope_kernel(float* __restrict__ qkv,
                            const float* __restrict__ ct,
                            const float* __restrict__ st)
{
    int idx = blockIdx.x * blockDim.x + threadIdx.x;
    if (idx >= M_TOK * 2 * H_ * 64) return;
    int d     = idx & 63;
    int h     = (idx >> 6) & 15;
    int which = (idx >> 10) & 1;
    int bs    = idx >> 11;
    int s     = bs & (S_ - 1);

    size_t base = (size_t)bs * QKV_N + (size_t)which * DM_ + h * HD_ + d;
    float lo = qkv[base];
    float hi = qkv[base + 64];
    float c  = ct[(s << 6) + d];
    float sn = st[(s << 6) + d];
    qkv[base]      = lo * c - hi * sn;
    qkv[base + 64] = hi * c + lo * sn;
}

// ---------------------------------------------------------------------------
// Causal flash attention fp32 (unchanged — next round's target)
// ---------------------------------------------------------------------------
#define AQ    64
#define AKV   64
#define QKSTR 132
#define PSTR  65
#define ATT_SMEM ((3 * AQ * QKSTR + AQ * PSTR) * 4)

__global__ __launch_bounds__(256) void attn_kernel(
    const float* __restrict__ qkv, float* __restrict__ out)
{
    extern __shared__ float smf[];
    float* Qs = smf;
    float* Ks = Qs + AQ * QKSTR;
    float* Vs = Ks + AKV * QKSTR;
    float* Ps = Vs + AKV * QKSTR;

    const int qb  = (gridDim.x - 1) - blockIdx.x;
    const int h   = blockIdx.y;
    const int b   = blockIdx.z;
    const int tid = threadIdx.x;
    const int tx  = tid & 15;
    const int ty  = tid >> 4;

    const int q0 = qb * AQ;
    const size_t tok0 = (size_t)b * S_;

    {
        const float* qbase = qkv + (tok0 + q0) * QKV_N + h * HD_;
#pragma unroll
        for (int it = 0; it < 8; ++it) {
            int slot = tid + it * 256;
            int r  = slot >> 5;
            int d4 = (slot & 31) << 2;
            *(float4*)(Qs + r * QKSTR + d4) =
                *(const float4*)(qbase + (size_t)r * QKV_N + d4);
        }
    }

    float m_i[4], l_i[4], o_acc[4][8];
#pragma unroll
    for (int i = 0; i < 4; ++i) {
        m_i[i] = -INFINITY;
        l_i[i] = 0.f;
#pragma unroll
        for (int k = 0; k < 8; ++k) o_acc[i][k] = 0.f;
    }

    const float scale = 0.08838834764831845f;

    for (int kb = 0; kb <= qb; ++kb) {
        __syncthreads();
        {
            const float* kbase = qkv + (tok0 + kb * AKV) * QKV_N + DM_ + h * HD_;
            const float* vbase = kbase + DM_;
#pragma unroll
            for (int it = 0; it < 8; ++it) {
                int slot = tid + it * 256;
                int r  = slot >> 5;
                int d4 = (slot & 31) << 2;
                *(float4*)(Ks + r * QKSTR + d4) =
                    *(const float4*)(kbase + (size_t)r * QKV_N + d4);
                *(float4*)(Vs + r * QKSTR + d4) =
                    *(const float4*)(vbase + (size_t)r * QKV_N + d4);
            }
        }
        __syncthreads();

        float s[4][4];
#pragma unroll
        for (int i = 0; i < 4; ++i)
#pragma unroll
            for (int j = 0; j < 4; ++j) s[i][j] = 0.f;

#pragma unroll 4
        for (int d4 = 0; d4 < HD_; d4 += 4) {
            float4 qv[4], kv[4];
#pragma unroll
            for (int i = 0; i < 4; ++i)
                qv[i] = *(const float4*)(Qs + (ty + 16 * i) * QKSTR + d4);
#pragma unroll
            for (int j = 0; j < 4; ++j)
                kv[j] = *(const float4*)(Ks + (tx + 16 * j) * QKSTR + d4);
#pragma unroll
            for (int i = 0; i < 4; ++i)
#pragma unroll
                for (int j = 0; j < 4; ++j) {
                    s[i][j] = fmaf(qv[i].x, kv[j].x, s[i][j]);
                    s[i][j] = fmaf(qv[i].y, kv[j].y, s[i][j]);
                    s[i][j] = fmaf(qv[i].z, kv[j].z, s[i][j]);
                    s[i][j] = fmaf(qv[i].w, kv[j].w, s[i][j]);
                }
        }

        const bool diag = (kb == qb);
#pragma unroll
        for (int i = 0; i < 4; ++i) {
            int rg = q0 + ty + 16 * i;
#pragma unroll
            for (int j = 0; j < 4; ++j) {
                int cg = kb * AKV + tx + 16 * j;
                s[i][j] = (diag && (cg > rg)) ? -INFINITY : s[i][j] * scale;
            }
        }

#pragma unroll
        for (int i = 0; i < 4; ++i) {
            float mx = fmaxf(fmaxf(s[i][0], s[i][1]), fmaxf(s[i][2], s[i][3]));
#pragma unroll
            for (int off = 8; off > 0; off >>= 1)
                mx = fmaxf(mx, __shfl_xor_sync(0xffffffffu, mx, off, 16));
            float m_new = fmaxf(m_i[i], mx);
            float alpha = __expf(m_i[i] - m_new);
            float psum  = 0.f;
            int   r     = ty + 16 * i;
#pragma unroll
            for (int j = 0; j < 4; ++j) {
                float p = __expf(s[i][j] - m_new);
                psum += p;
                Ps[r * PSTR + tx + 16 * j] = p;
            }
#pragma unroll
            for (int off = 8; off > 0; off >>= 1)
                psum += __shfl_xor_sync(0xffffffffu, psum, off, 16);
            l_i[i] = l_i[i] * alpha + psum;
            m_i[i] = m_new;
#pragma unroll
            for (int k = 0; k < 8; ++k) o_acc[i][k] *= alpha;
        }
        __syncthreads();

#pragma unroll 4
        for (int k0 = 0; k0 < AKV; ++k0) {
            float4 v0 = *(const float4*)(Vs + k0 * QKSTR + tx * 8);
            float4 v1 = *(const float4*)(Vs + k0 * QKSTR + tx * 8 + 4);
#pragma unroll
            for (int i = 0; i < 4; ++i) {
                float p = Ps[(ty + 16 * i) * PSTR + k0];
                o_acc[i][0] = fmaf(p, v0.x, o_acc[i][0]);
                o_acc[i][1] = fmaf(p, v0.y, o_acc[i][1]);
                o_acc[i][2] = fmaf(p, v0.z, o_acc[i][2]);
                o_acc[i][3] = fmaf(p, v0.w, o_acc[i][3]);
                o_acc[i][4] = fmaf(p, v1.x, o_acc[i][4]);
                o_acc[i][5] = fmaf(p, v1.y, o_acc[i][5]);
                o_acc[i][6] = fmaf(p, v1.z, o_acc[i][6]);
                o_acc[i][7] = fmaf(p, v1.w, o_acc[i][7]);
            }
        }
    }

#pragma unroll
    for (int i = 0; i < 4; ++i) {
        float inv = 1.f / l_i[i];
        int   r   = ty + 16 * i;
        float* orow = out + (tok0 + q0 + r) * (size_t)DM_ + h * HD_ + tx * 8;
        float4 o0 = make_float4(o_acc[i][0] * inv, o_acc[i][1] * inv,
                                o_acc[i][2] * inv, o_acc[i][3] * inv);
        float4 o1 = make_float4(o_acc[i][4] * inv, o_acc[i][5] * inv,
                                o_acc[i][6] * inv, o_acc[i][7] * inv);
        *(float4*)(orow)     = o0;
        *(float4*)(orow + 4) = o1;
    }
}

// ---------------------------------------------------------------------------
// Launch
// ---------------------------------------------------------------------------
extern "C" void kernel_launch(void* const* d_in, const int* in_sizes, int n_in,
                              void* d_out, int out_size)
{
    (void)in_sizes; (void)n_in; (void)out_size;
    const float* x     = (const float*)d_in[0];
    const float* W_qkv = (const float*)d_in[1];
    const float* W_o   = (const float*)d_in[2];
    float* out = (float*)d_out;

    float *qkv, *attn, *ct, *st;
    __nv_bfloat16 *Ah, *Al, *Bh, *Bl, *Woh, *Wol;
    cudaGetSymbolAddress((void**)&qkv,  g_qkv);
    cudaGetSymbolAddress((void**)&attn, g_attn);
    cudaGetSymbolAddress((void**)&ct,   g_cos);
    cudaGetSymbolAddress((void**)&st,   g_sin);
    cudaGetSymbolAddress((void**)&Ah,   g_Ah);
    cudaGetSymbolAddress((void**)&Al,   g_Al);
    cudaGetSymbolAddress((void**)&Bh,   g_Bh);
    cudaGetSymbolAddress((void**)&Bl,   g_Bl);
    cudaGetSymbolAddress((void**)&Woh,  g_Woh);
    cudaGetSymbolAddress((void**)&Wol,  g_Wol);

    cudaFuncSetAttribute(gemm_mma_kernel,
                         cudaFuncAttributeMaxDynamicSharedMemorySize, GEMM_SMEM);
    cudaFuncSetAttribute(attn_kernel,
                         cudaFuncAttributeMaxDynamicSharedMemorySize, ATT_SMEM);

    // RoPE table
    rope_table_kernel<<<(S_ * 64 + 255) / 256, 256>>>(ct, st);

    // Split conversions
    conv_split_kernel<<<(M_TOK * D_ / 4 + 255) / 256, 256>>>(x, Ah, Al, M_TOK * D_ / 4);
    conv_tsplit_kernel<<<dim3(QKV_N / 32, D_ / 32), 256>>>(W_qkv, D_, QKV_N, Bh, Bl);
    conv_tsplit_kernel<<<dim3(DM_ / 32, D_ / 32), 256>>>(W_o, DM_, DM_, Woh, Wol);

    // qkv = x @ W_qkv (bf16x3 mma.sync)
    gemm_mma_kernel<<<dim3(QKV_N / 128, M_TOK / 128), 256, GEMM_SMEM>>>(
        Ah, Al, Bh, Bl, qkv, M_TOK, QKV_N, D_);

    // RoPE in place on q,k
    rope_kernel<<<(M_TOK * 2 * H_ * 64) / 256, 256>>>(qkv, ct, st);

    // causal attention -> attn
    attn_kernel<<<dim3(S_ / AQ, H_, B_), 256, ATT_SMEM>>>(qkv, attn);

    // split attn, then out = attn @ W_o (bf16x3 mma.sync)
    conv_split_kernel<<<(M_TOK * DM_ / 4 + 255) / 256, 256>>>(attn, Ah, Al, M_TOK * DM_ / 4);
    gemm_mma_kernel<<<dim3(DM_ / 128, M_TOK / 128), 256, GEMM_SMEM>>>(
        Ah, Al, Woh, Wol, out, M_TOK, DM_, D_);
}

// round 4
// speedup vs baseline: 2.3473x; 1.5084x over previous
#include <cuda_runtime.h>
#include <cuda_bf16.h>
#include <math.h>
#include <stdint.h>

// Problem constants
#define B_    2
#define S_    2048
#define D_    2048
#define H_    16
#define HD_   128
#define M_TOK (B_ * S_)          // 4096 tokens
#define QKV_N (3 * H_ * HD_)     // 6144
#define DM_   (H_ * HD_)         // 2048

// ---------------------------------------------------------------------------
// Scratch (__device__ globals; no allocation allowed)
// ---------------------------------------------------------------------------
__device__ float g_qkv[(size_t)M_TOK * QKV_N];            // 100.7 MB
__device__ float g_cos[S_ * (HD_ / 2)];
__device__ float g_sin[S_ * (HD_ / 2)];
__device__ __nv_bfloat16 g_Ah[(size_t)M_TOK * D_];        // GEMM A hi (x, later O)
__device__ __nv_bfloat16 g_Al[(size_t)M_TOK * D_];        // GEMM A lo
__device__ __nv_bfloat16 g_Bh[(size_t)QKV_N * D_];        // W_qkv^T hi [N][K]
__device__ __nv_bfloat16 g_Bl[(size_t)QKV_N * D_];
__device__ __nv_bfloat16 g_Woh[(size_t)DM_ * D_];         // W_o^T hi [N][K]
__device__ __nv_bfloat16 g_Wol[(size_t)DM_ * D_];
// attention operands, head-major
__device__ __nv_bfloat16 g_Qh[(size_t)M_TOK * DM_];       // [b,h,s,hd] (pre-scaled)
__device__ __nv_bfloat16 g_Ql[(size_t)M_TOK * DM_];
__device__ __nv_bfloat16 g_Kh[(size_t)M_TOK * DM_];
__device__ __nv_bfloat16 g_Kl[(size_t)M_TOK * DM_];
__device__ __nv_bfloat16 g_Vth[(size_t)M_TOK * DM_];      // [b,h,hd,s]
__device__ __nv_bfloat16 g_Vtl[(size_t)M_TOK * DM_];

// ---------------------------------------------------------------------------
// Arch-generic PTX helpers (NO tcgen05 — compute_103 target rejects it)
// ---------------------------------------------------------------------------
__device__ __forceinline__ uint32_t smem_u32(const void* p) {
    uint32_t a;
    asm("{ .reg .u64 t; cvta.to.shared.u64 t, %1; cvt.u32.u64 %0, t; }"
        : "=r"(a) : "l"(p));
    return a;
}
#define CP16(dst, src) \
    asm volatile("cp.async.cg.shared.global [%0], [%1], 16;" :: "r"(dst), "l"(src) : "memory")
#define CP_COMMIT() asm volatile("cp.async.commit_group;" ::: "memory")
#define CP_WAIT(n)  asm volatile("cp.async.wait_group %0;" :: "n"(n) : "memory")

__device__ __forceinline__ void ldsm4(uint32_t* r, uint32_t addr) {
    asm volatile("ldmatrix.sync.aligned.m8n8.x4.shared.b16 {%0,%1,%2,%3}, [%4];"
                 : "=r"(r[0]), "=r"(r[1]), "=r"(r[2]), "=r"(r[3]) : "r"(addr));
}
__device__ __forceinline__ void mma16816(float* c, const uint32_t* a, const uint32_t* b) {
    asm volatile(
        "mma.sync.aligned.m16n8k16.row.col.f32.bf16.bf16.f32 "
        "{%0,%1,%2,%3}, {%4,%5,%6,%7}, {%8,%9}, {%0,%1,%2,%3};"
        : "+f"(c[0]), "+f"(c[1]), "+f"(c[2]), "+f"(c[3])
        : "r"(a[0]), "r"(a[1]), "r"(a[2]), "r"(a[3]), "r"(b[0]), "r"(b[1]));
}
__device__ __forceinline__ uint32_t pack_bf16(float x, float y) {
    __nv_bfloat162 t = __float22bfloat162_rn(make_float2(x, y));
    return *(uint32_t*)&t;
}

// ---------------------------------------------------------------------------
// bf16x3 MMA GEMM (unchanged from R3): C[M,N] = A[M,K] @ B^T, B stored [N][K]
// ---------------------------------------------------------------------------
#define GSTR  40
#define TILE_E (128 * GSTR)
#define STG_E  (4 * TILE_E)
#define GEMM_SMEM (2 * STG_E * 2)

__global__ __launch_bounds__(256) void gemm_mma_kernel(
    const __nv_bfloat16* __restrict__ Ah, const __nv_bfloat16* __restrict__ Al,
    const __nv_bfloat16* __restrict__ Bh, const __nv_bfloat16* __restrict__ Bl,
    float* __restrict__ C, int M, int N, int K)
{
    extern __shared__ __nv_bfloat16 sm[];
    const uint32_t sbase = smem_u32(sm);
    const int tid  = threadIdx.x;
    const int lane = tid & 31;
    const int wid  = tid >> 5;
    const int bm = blockIdx.y * 128;
    const int bn = blockIdx.x * 128;
    const int wm = (wid & 3) * 32;
    const int wn = (wid >> 2) * 64;

    float acc[2][8][4];
#pragma unroll
    for (int mt = 0; mt < 2; ++mt)
#pragma unroll
        for (int nt = 0; nt < 8; ++nt)
#pragma unroll
            for (int v = 0; v < 4; ++v) acc[mt][nt][v] = 0.f;

    auto load_chunk = [&](int stage, int kc) {
#pragma unroll
        for (int j = 0; j < 8; ++j) {
            int s = tid + j * 256;
            int tile = s >> 9;
            int r = (s >> 2) & 127;
            int c = s & 3;
            const __nv_bfloat16* p =
                (tile == 0) ? Ah : (tile == 1) ? Al : (tile == 2) ? Bh : Bl;
            int rb = (tile < 2) ? bm : bn;
            const __nv_bfloat16* src = p + (size_t)(rb + r) * K + kc + c * 8;
            uint32_t dst = sbase + (uint32_t)(stage * STG_E + tile * TILE_E +
                                              r * GSTR + c * 8) * 2u;
            CP16(dst, src);
        }
    };

    const int NC = K / 32;
    load_chunk(0, 0);
    CP_COMMIT();

    for (int i = 0; i < NC; ++i) {
        if (i + 1 < NC) {
            load_chunk((i + 1) & 1, (i + 1) * 32);
            CP_COMMIT();
            CP_WAIT(1);
        } else {
            CP_WAIT(0);
        }
        __syncthreads();

        const uint32_t sA  = sbase + (uint32_t)((i & 1) * STG_E) * 2u;
        const uint32_t dAl = TILE_E * 2u;
        const uint32_t dB  = 2u * TILE_E * 2u;

#pragma unroll
        for (int ks = 0; ks < 32; ks += 16) {
            uint32_t ah[2][4], al[2][4], bh[8][2], bl[8][2];
#pragma unroll
            for (int mt = 0; mt < 2; ++mt) {
                uint32_t ra = sA + (uint32_t)((wm + mt * 16 + (lane & 15)) * GSTR +
                                              ks + (lane >> 4) * 8) * 2u;
                ldsm4(ah[mt], ra);
                ldsm4(al[mt], ra + dAl);
            }
#pragma unroll
            for (int p = 0; p < 4; ++p) {
                uint32_t rb = sA + dB + (uint32_t)((wn + p * 16 + (lane & 15)) * GSTR +
                                                   ks + (lane >> 4) * 8) * 2u;
                uint32_t t[4];
                ldsm4(t, rb);
                bh[2 * p][0] = t[0]; bh[2 * p + 1][0] = t[1];
                bh[2 * p][1] = t[2]; bh[2 * p + 1][1] = t[3];
                ldsm4(t, rb + dAl);
                bl[2 * p][0] = t[0]; bl[2 * p + 1][0] = t[1];
                bl[2 * p][1] = t[2]; bl[2 * p + 1][1] = t[3];
            }
#pragma unroll
            for (int mt = 0; mt < 2; ++mt)
#pragma unroll
                for (int nt = 0; nt < 8; ++nt) mma16816(acc[mt][nt], ah[mt], bh[nt]);
#pragma unroll
            for (int mt = 0; mt < 2; ++mt)
#pragma unroll
                for (int nt = 0; nt < 8; ++nt) mma16816(acc[mt][nt], ah[mt], bl[nt]);
#pragma unroll
            for (int mt = 0; mt < 2; ++mt)
#pragma unroll
                for (int nt = 0; nt < 8; ++nt) mma16816(acc[mt][nt], al[mt], bh[nt]);
        }
        __syncthreads();
    }

#pragma unroll
    for (int mt = 0; mt < 2; ++mt) {
        int row = bm + wm + mt * 16 + (lane >> 2);
#pragma unroll
        for (int nt = 0; nt < 8; ++nt) {
            int col = bn + wn + nt * 8 + (lane & 3) * 2;
            *(float2*)&C[(size_t)row * N + col] =
                make_float2(acc[mt][nt][0], acc[mt][nt][1]);
            *(float2*)&C[(size_t)(row + 8) * N + col] =
                make_float2(acc[mt][nt][2], acc[mt][nt][3]);
        }
    }
}

// ---------------------------------------------------------------------------
// fp32 -> bf16 hi/lo split
// ---------------------------------------------------------------------------
__global__ void conv_split_kernel(const float* __restrict__ X,
                                  __nv_bfloat16* __restrict__ Xh,
                                  __nv_bfloat16* __restrict__ Xl, int n4)
{
    int i = blockIdx.x * blockDim.x + threadIdx.x;
    if (i >= n4) return;
    float4 v = *(const float4*)(X + (size_t)i * 4);
    __nv_bfloat162 h01 = __floats2bfloat162_rn(v.x, v.y);
    __nv_bfloat162 h23 = __floats2bfloat162_rn(v.z, v.w);
    float2 f01 = __bfloat1622float2(h01);
    float2 f23 = __bfloat1622float2(h23);
    __nv_bfloat162 l01 = __floats2bfloat162_rn(v.x - f01.x, v.y - f01.y);
    __nv_bfloat162 l23 = __floats2bfloat162_rn(v.z - f23.x, v.w - f23.y);
    *(__nv_bfloat162*)(Xh + (size_t)i * 4)     = h01;
    *(__nv_bfloat162*)(Xh + (size_t)i * 4 + 2) = h23;
    *(__nv_bfloat162*)(Xl + (size_t)i * 4)     = l01;
    *(__nv_bfloat162*)(Xl + (size_t)i * 4 + 2) = l23;
}

// ---------------------------------------------------------------------------
// fp32 W[R,C] -> transposed bf16 hi/lo T[C,R]
// ---------------------------------------------------------------------------
__global__ __launch_bounds__(256) void conv_tsplit_kernel(
    const float* __restrict__ W, int R, int C,
    __nv_bfloat16* __restrict__ Th, __nv_bfloat16* __restrict__ Tl)
{
    __shared__ float t[32][33];
    const int c0 = blockIdx.x * 32, r0 = blockIdx.y * 32;
    const int tx = threadIdx.x & 31, ty = threadIdx.x >> 5;
#pragma unroll
    for (int i = 0; i < 32; i += 8)
        t[ty + i][tx] = W[(size_t)(r0 + ty + i) * C + c0 + tx];
    __syncthreads();
#pragma unroll
    for (int i = 0; i < 32; i += 8) {
        float v = t[tx][ty + i];
        __nv_bfloat16 h = __float2bfloat16(v);
        __nv_bfloat16 l = __float2bfloat16(v - __bfloat162float(h));
        size_t o = (size_t)(c0 + ty + i) * R + r0 + tx;
        Th[o] = h;
        Tl[o] = l;
    }
}

// ---------------------------------------------------------------------------
// RoPE table
// ---------------------------------------------------------------------------
__global__ void rope_table_kernel(float* __restrict__ ct, float* __restrict__ st)
{
    int idx = blockIdx.x * blockDim.x + threadIdx.x;
    if (idx >= S_ * 64) return;
    int d = idx & 63;
    int s = idx >> 6;
    float inv_freq = 1.0f / powf(10000.0f, (float)d * (1.0f / 64.0f));
    float ang = (float)s * inv_freq;
    ct[idx] = (float)cos((double)ang);
    st[idx] = (float)sin((double)ang);
}

// ---------------------------------------------------------------------------
// RoPE + hi/lo split for Q (pre-scaled by HD^-1/2) and K, head-major output.
// One thread per (token, which, head, d<64).
// ---------------------------------------------------------------------------
__global__ void rope_split_kernel(
    const float* __restrict__ qkv,
    const float* __restrict__ ct, const float* __restrict__ st,
    __nv_bfloat16* __restrict__ Qh, __nv_bfloat16* __restrict__ Ql,
    __nv_bfloat16* __restrict__ Kh, __nv_bfloat16* __restrict__ Kl)
{
    int idx = blockIdx.x * blockDim.x + threadIdx.x;
    if (idx >= M_TOK * 2 * H_ * 64) return;
    int d     = idx & 63;
    int h     = (idx >> 6) & 15;
    int which = (idx >> 10) & 1;
    int bs    = idx >> 11;
    int b     = bs >> 11;
    int s     = bs & (S_ - 1);

    size_t base = (size_t)bs * QKV_N + (size_t)which * DM_ + h * HD_ + d;
    float lo = qkv[base];
    float hi = qkv[base + 64];
    float c  = ct[(s << 6) + d];
    float sn = st[(s << 6) + d];
    float e0 = lo * c - hi * sn;
    float e1 = hi * c + lo * sn;
    if (which == 0) {                 // fold 128^-0.5 into Q
        e0 *= 0.08838834764831845f;
        e1 *= 0.08838834764831845f;
    }
    size_t dst = ((size_t)(b * H_ + h) * S_ + s) * HD_ + d;
    __nv_bfloat16* Ph = which ? Kh : Qh;
    __nv_bfloat16* Pl = which ? Kl : Ql;
    __nv_bfloat16 h0 = __float2bfloat16(e0);
    __nv_bfloat16 h1 = __float2bfloat16(e1);
    Ph[dst]      = h0;
    Ph[dst + 64] = h1;
    Pl[dst]      = __float2bfloat16(e0 - __bfloat162float(h0));
    Pl[dst + 64] = __float2bfloat16(e1 - __bfloat162float(h1));
}

// ---------------------------------------------------------------------------
// V -> transposed hi/lo split: Vt[b,h,hd,s]
// grid (HD/32, S/32, B*H), block 256
// ---------------------------------------------------------------------------
__global__ __launch_bounds__(256) void v_tsplit_kernel(
    const float* __restrict__ qkv,
    __nv_bfloat16* __restrict__ Vth, __nv_bfloat16* __restrict__ Vtl)
{
    __shared__ float t[32][33];
    const int d0 = blockIdx.x * 32, s0 = blockIdx.y * 32;
    const int bh = blockIdx.z;
    const int b = bh >> 4, h = bh & 15;
    const int tx = threadIdx.x & 31, ty = threadIdx.x >> 5;
#pragma unroll
    for (int i = 0; i < 32; i += 8)
        t[ty + i][tx] = qkv[(size_t)(b * S_ + s0 + ty + i) * QKV_N +
                            2 * DM_ + h * HD_ + d0 + tx];
    __syncthreads();
#pragma unroll
    for (int i = 0; i < 32; i += 8) {
        float v = t[tx][ty + i];
        __nv_bfloat16 hi = __float2bfloat16(v);
        __nv_bfloat16 lo = __float2bfloat16(v - __bfloat162float(hi));
        size_t o = ((size_t)bh * HD_ + d0 + ty + i) * S_ + s0 + tx;
        Vth[o] = hi;
        Vtl[o] = lo;
    }
}

// ---------------------------------------------------------------------------
// Flash attention, bf16x3 mma.sync.
// CTA: 64 q-rows x full KV sweep, tiles of 64 kv. 4 warps, each owns 16 q rows.
// Scores = Qs(pre-scaled)·K^T via 3-split MMA; online softmax on fragments;
// P repacked in registers (hi+lo); O += P·Vt^T via 3-split MMA.
// Output written directly as bf16 hi/lo GEMM2 A operand [token][h*128+d].
// ---------------------------------------------------------------------------
#define QSTR 136
#define VSTR 72
#define QH_OFF 0u
#define QL_OFF (64u * QSTR * 2u)
#define KH_OFF (2u * 64u * QSTR * 2u)
#define KL_OFF (3u * 64u * QSTR * 2u)
#define VH_OFF (4u * 64u * QSTR * 2u)
#define VL_OFF (VH_OFF + 128u * VSTR * 2u)
#define ATT_SMEM (VL_OFF + 128u * VSTR * 2u)   // 106496 bytes

__global__ __launch_bounds__(128) void attn_mma_kernel(
    const __nv_bfloat16* __restrict__ Qh, const __nv_bfloat16* __restrict__ Ql,
    const __nv_bfloat16* __restrict__ Kh, const __nv_bfloat16* __restrict__ Kl,
    const __nv_bfloat16* __restrict__ Vth, const __nv_bfloat16* __restrict__ Vtl,
    __nv_bfloat16* __restrict__ Oh, __nv_bfloat16* __restrict__ Ol)
{
    extern __shared__ char asm_[];
    const uint32_t sb = smem_u32(asm_);
    const int tid  = threadIdx.x;
    const int lane = tid & 31;
    const int wid  = tid >> 5;
    const int qb = (int)(gridDim.x - 1) - (int)blockIdx.x;   // heavy first
    const int h  = blockIdx.y;
    const int b  = blockIdx.z;
    const int bh = b * H_ + h;
    const int q0 = qb * 64;
    const int wq = wid * 16;

    // ---- load Q tile (hi+lo) once ----
    {
        const __nv_bfloat16* q_h = Qh + ((size_t)bh * S_ + q0) * HD_;
        const __nv_bfloat16* q_l = Ql + ((size_t)bh * S_ + q0) * HD_;
#pragma unroll
        for (int j = 0; j < 16; ++j) {
            int s = tid + j * 128;
            int hi = s < 1024;
            int u = s & 1023;
            int r = u >> 4, c = u & 15;
            const __nv_bfloat16* src = (hi ? q_h : q_l) + (size_t)r * HD_ + c * 8;
            CP16(sb + (hi ? QH_OFF : QL_OFF) + (uint32_t)(r * QSTR + c * 8) * 2u, src);
        }
    }
    CP_COMMIT();

    float acc[16][4];
#pragma unroll
    for (int nt = 0; nt < 16; ++nt)
#pragma unroll
        for (int v = 0; v < 4; ++v) acc[nt][v] = 0.f;
    float m0 = -INFINITY, m1 = -INFINITY, l0 = 0.f, l1 = 0.f;

    const int r0 = lane >> 2;            // local row within warp m16
    const int rg0 = q0 + wq + r0;        // global q row (row 1 = +8)

    const __nv_bfloat16* k_h = Kh + ((size_t)bh * S_) * HD_;
    const __nv_bfloat16* k_l = Kl + ((size_t)bh * S_) * HD_;
    const __nv_bfloat16* v_h = Vth + (size_t)bh * HD_ * S_;
    const __nv_bfloat16* v_l = Vtl + (size_t)bh * HD_ * S_;

    for (int kb = 0; kb <= qb; ++kb) {
        const int kv0 = kb * 64;
        __syncthreads();                 // previous iter done reading K/V
        // ---- load K (64x128) and Vt (128x64) hi+lo ----
#pragma unroll
        for (int j = 0; j < 16; ++j) {
            int s = tid + j * 128;
            int hi = s < 1024;
            int u = s & 1023;
            int r = u >> 4, c = u & 15;
            const __nv_bfloat16* src = (hi ? k_h : k_l) + (size_t)(kv0 + r) * HD_ + c * 8;
            CP16(sb + (hi ? KH_OFF : KL_OFF) + (uint32_t)(r * QSTR + c * 8) * 2u, src);
        }
#pragma unroll
        for (int j = 0; j < 16; ++j) {
            int s = tid + j * 128;
            int hi = s < 1024;
            int u = s & 1023;
            int r = u >> 3, c = u & 7;
            const __nv_bfloat16* src = (hi ? v_h : v_l) + (size_t)r * S_ + kv0 + c * 8;
            CP16(sb + (hi ? VH_OFF : VL_OFF) + (uint32_t)(r * VSTR + c * 8) * 2u, src);
        }
        CP_COMMIT();
        CP_WAIT(0);
        __syncthreads();

        // ---- scores: sc[8 n-tiles][4] ----
        float sc[8][4];
#pragma unroll
        for (int nt = 0; nt < 8; ++nt)
#pragma unroll
            for (int v = 0; v < 4; ++v) sc[nt][v] = 0.f;

#pragma unroll
        for (int ks = 0; ks < 8; ++ks) {
            uint32_t a_h[4], a_l[4], b_h[8][2], b_l[8][2];
            uint32_t ra = sb + QH_OFF + (uint32_t)((wq + (lane & 15)) * QSTR +
                                                   ks * 16 + (lane >> 4) * 8) * 2u;
            ldsm4(a_h, ra);
            ldsm4(a_l, ra + QL_OFF);
#pragma unroll
            for (int p = 0; p < 4; ++p) {
                uint32_t rb = sb + KH_OFF + (uint32_t)((p * 16 + (lane & 15)) * QSTR +
                                                       ks * 16 + (lane >> 4) * 8) * 2u;
                uint32_t t[4];
                ldsm4(t, rb);
                b_h[2 * p][0] = t[0]; b_h[2 * p + 1][0] = t[1];
                b_h[2 * p][1] = t[2]; b_h[2 * p + 1][1] = t[3];
                ldsm4(t, rb + (KL_OFF - KH_OFF));
                b_l[2 * p][0] = t[0]; b_l[2 * p + 1][0] = t[1];
                b_l[2 * p][1] = t[2]; b_l[2 * p + 1][1] = t[3];
            }
#pragma unroll
            for (int nt = 0; nt < 8; ++nt) mma16816(sc[nt], a_h, b_h[nt]);
#pragma unroll
            for (int nt = 0; nt < 8; ++nt) mma16816(sc[nt], a_h, b_l[nt]);
#pragma unroll
            for (int nt = 0; nt < 8; ++nt) mma16816(sc[nt], a_l, b_h[nt]);
        }

        // ---- causal mask (diagonal tile only) ----
        if (kb == qb) {
#pragma unroll
            for (int nt = 0; nt < 8; ++nt) {
                int c0 = kv0 + nt * 8 + (lane & 3) * 2;
                if (c0     > rg0)     sc[nt][0] = -INFINITY;
                if (c0 + 1 > rg0)     sc[nt][1] = -INFINITY;
                if (c0     > rg0 + 8) sc[nt][2] = -INFINITY;
                if (c0 + 1 > rg0 + 8) sc[nt][3] = -INFINITY;
            }
        }

        // ---- online softmax on fragments ----
        float mx0 = -INFINITY, mx1 = -INFINITY;
#pragma unroll
        for (int nt = 0; nt < 8; ++nt) {
            mx0 = fmaxf(mx0, fmaxf(sc[nt][0], sc[nt][1]));
            mx1 = fmaxf(mx1, fmaxf(sc[nt][2], sc[nt][3]));
        }
        mx0 = fmaxf(mx0, __shfl_xor_sync(0xffffffffu, mx0, 1));
        mx0 = fmaxf(mx0, __shfl_xor_sync(0xffffffffu, mx0, 2));
        mx1 = fmaxf(mx1, __shfl_xor_sync(0xffffffffu, mx1, 1));
        mx1 = fmaxf(mx1, __shfl_xor_sync(0xffffffffu, mx1, 2));
        float m0n = fmaxf(m0, mx0), m1n = fmaxf(m1, mx1);
        float al0 = __expf(m0 - m0n), al1 = __expf(m1 - m1n);
        float ps0 = 0.f, ps1 = 0.f;
#pragma unroll
        for (int nt = 0; nt < 8; ++nt) {
            sc[nt][0] = __expf(sc[nt][0] - m0n);
            sc[nt][1] = __expf(sc[nt][1] - m0n);
            sc[nt][2] = __expf(sc[nt][2] - m1n);
            sc[nt][3] = __expf(sc[nt][3] - m1n);
            ps0 += sc[nt][0] + sc[nt][1];
            ps1 += sc[nt][2] + sc[nt][3];
        }
        ps0 += __shfl_xor_sync(0xffffffffu, ps0, 1);
        ps0 += __shfl_xor_sync(0xffffffffu, ps0, 2);
        ps1 += __shfl_xor_sync(0xffffffffu, ps1, 1);
        ps1 += __shfl_xor_sync(0xffffffffu, ps1, 2);
        l0 = l0 * al0 + ps0;
        l1 = l1 * al1 + ps1;
        m0 = m0n; m1 = m1n;
#pragma unroll
        for (int nt = 0; nt < 16; ++nt) {
            acc[nt][0] *= al0; acc[nt][1] *= al0;
            acc[nt][2] *= al1; acc[nt][3] *= al1;
        }

        // ---- pack P (hi + residual lo) into A fragments per k-step ----
        uint32_t phk[4][4], plk[4][4];
#pragma unroll
        for (int kt = 0; kt < 4; ++kt) {
#pragma unroll
            for (int half = 0; half < 2; ++half) {
                int j = 2 * kt + half;
                uint32_t p01 = pack_bf16(sc[j][0], sc[j][1]);
                uint32_t p23 = pack_bf16(sc[j][2], sc[j][3]);
                float2 f01 = __bfloat1622float2(*(__nv_bfloat162*)&p01);
                float2 f23 = __bfloat1622float2(*(__nv_bfloat162*)&p23);
                phk[kt][half * 2 + 0] = p01;           // a0 / a2
                phk[kt][half * 2 + 1] = p23;           // a1 / a3
                plk[kt][half * 2 + 0] = pack_bf16(sc[j][0] - f01.x, sc[j][1] - f01.y);
                plk[kt][half * 2 + 1] = pack_bf16(sc[j][2] - f23.x, sc[j][3] - f23.y);
            }
        }

        // ---- O += P @ V (16 n-tiles in two halves of 8) ----
#pragma unroll
        for (int kt = 0; kt < 4; ++kt) {
#pragma unroll
            for (int hlf = 0; hlf < 2; ++hlf) {
                uint32_t bvh[8][2], bvl[8][2];
#pragma unroll
                for (int p = 0; p < 4; ++p) {
                    uint32_t rb = sb + VH_OFF +
                        (uint32_t)((hlf * 64 + p * 16 + (lane & 15)) * VSTR +
                                   kt * 16 + (lane >> 4) * 8) * 2u;
                    uint32_t t[4];
                    ldsm4(t, rb);
                    bvh[2 * p][0] = t[0]; bvh[2 * p + 1][0] = t[1];
                    bvh[2 * p][1] = t[2]; bvh[2 * p + 1][1] = t[3];
                    ldsm4(t, rb + (VL_OFF - VH_OFF));
                    bvl[2 * p][0] = t[0]; bvl[2 * p + 1][0] = t[1];
                    bvl[2 * p][1] = t[2]; bvl[2 * p + 1][1] = t[3];
                }
#pragma unroll
                for (int nt = 0; nt < 8; ++nt) mma16816(acc[hlf * 8 + nt], phk[kt], bvh[nt]);
#pragma unroll
                for (int nt = 0; nt < 8; ++nt) mma16816(acc[hlf * 8 + nt], phk[kt], bvl[nt]);
#pragma unroll
                for (int nt = 0; nt < 8; ++nt) mma16816(acc[hlf * 8 + nt], plk[kt], bvh[nt]);
            }
        }
    }

    // ---- finalize + write O as bf16 hi/lo (GEMM2 A operand) ----
    float inv0 = 1.f / l0, inv1 = 1.f / l1;
    size_t tok0 = (size_t)b * S_ + q0 + wq + r0;
#pragma unroll
    for (int nt = 0; nt < 16; ++nt) {
        int col = h * HD_ + nt * 8 + (lane & 3) * 2;
        {
            float o0 = acc[nt][0] * inv0, o1 = acc[nt][1] * inv0;
            uint32_t hi = pack_bf16(o0, o1);
            float2 f = __bfloat1622float2(*(__nv_bfloat162*)&hi);
            uint32_t lo = pack_bf16(o0 - f.x, o1 - f.y);
            *(uint32_t*)&Oh[tok0 * DM_ + col] = hi;
            *(uint32_t*)&Ol[tok0 * DM_ + col] = lo;
        }
        {
            float o0 = acc[nt][2] * inv1, o1 = acc[nt][3] * inv1;
            uint32_t hi = pack_bf16(o0, o1);
            float2 f = __bfloat1622float2(*(__nv_bfloat162*)&hi);
            uint32_t lo = pack_bf16(o0 - f.x, o1 - f.y);
            *(uint32_t*)&Oh[(tok0 + 8) * DM_ + col] = hi;
            *(uint32_t*)&Ol[(tok0 + 8) * DM_ + col] = lo;
        }
    }
}

// ---------------------------------------------------------------------------
// Launch
// ---------------------------------------------------------------------------
extern "C" void kernel_launch(void* const* d_in, const int* in_sizes, int n_in,
                              void* d_out, int out_size)
{
    (void)in_sizes; (void)n_in; (void)out_size;
    const float* x     = (const float*)d_in[0];
    const float* W_qkv = (const float*)d_in[1];
    const float* W_o   = (const float*)d_in[2];
    float* out = (float*)d_out;

    float *qkv, *ct, *st;
    __nv_bfloat16 *Ah, *Al, *Bh, *Bl, *Woh, *Wol;
    __nv_bfloat16 *Qh, *Ql, *Kh, *Kl, *Vth, *Vtl;
    cudaGetSymbolAddress((void**)&qkv,  g_qkv);
    cudaGetSymbolAddress((void**)&ct,   g_cos);
    cudaGetSymbolAddress((void**)&st,   g_sin);
    cudaGetSymbolAddress((void**)&Ah,   g_Ah);
    cudaGetSymbolAddress((void**)&Al,   g_Al);
    cudaGetSymbolAddress((void**)&Bh,   g_Bh);
    cudaGetSymbolAddress((void**)&Bl,   g_Bl);
    cudaGetSymbolAddress((void**)&Woh,  g_Woh);
    cudaGetSymbolAddress((void**)&Wol,  g_Wol);
    cudaGetSymbolAddress((void**)&Qh,   g_Qh);
    cudaGetSymbolAddress((void**)&Ql,   g_Ql);
    cudaGetSymbolAddress((void**)&Kh,   g_Kh);
    cudaGetSymbolAddress((void**)&Kl,   g_Kl);
    cudaGetSymbolAddress((void**)&Vth,  g_Vth);
    cudaGetSymbolAddress((void**)&Vtl,  g_Vtl);

    cudaFuncSetAttribute(gemm_mma_kernel,
                         cudaFuncAttributeMaxDynamicSharedMemorySize, GEMM_SMEM);
    cudaFuncSetAttribute(attn_mma_kernel,
                         cudaFuncAttributeMaxDynamicSharedMemorySize, ATT_SMEM);

    rope_table_kernel<<<(S_ * 64 + 255) / 256, 256>>>(ct, st);

    conv_split_kernel<<<(M_TOK * D_ / 4 + 255) / 256, 256>>>(x, Ah, Al, M_TOK * D_ / 4);
    conv_tsplit_kernel<<<dim3(QKV_N / 32, D_ / 32), 256>>>(W_qkv, D_, QKV_N, Bh, Bl);
    conv_tsplit_kernel<<<dim3(DM_ / 32, D_ / 32), 256>>>(W_o, DM_, DM_, Woh, Wol);

    // qkv = x @ W_qkv
    gemm_mma_kernel<<<dim3(QKV_N / 128, M_TOK / 128), 256, GEMM_SMEM>>>(
        Ah, Al, Bh, Bl, qkv, M_TOK, QKV_N, D_);

    // RoPE + split to head-major attention operands
    rope_split_kernel<<<(M_TOK * 2 * H_ * 64) / 256, 256>>>(
        qkv, ct, st, Qh, Ql, Kh, Kl);
    v_tsplit_kernel<<<dim3(HD_ / 32, S_ / 32, B_ * H_), 256>>>(qkv, Vth, Vtl);

    // causal flash attention (bf16x3 mma) -> writes Ah/Al (GEMM2 operand)
    attn_mma_kernel<<<dim3(S_ / 64, H_, B_), 128, ATT_SMEM>>>(
        Qh, Ql, Kh, Kl, Vth, Vtl, Ah, Al);

    // out = attn @ W_o
    gemm_mma_kernel<<<dim3(DM_ / 128, M_TOK / 128), 256, GEMM_SMEM>>>(
        Ah, Al, Woh, Wol, out, M_TOK, DM_, D_);
}